// round 17
// baseline (speedup 1.0000x reference)
#include <cuda_runtime.h>

// PWC-Net correlation (MAX_DISP=4 -> 81 channels) + LeakyReLU(0.1), /C normalize.
// feat1, feat2: [N=8, C=256, H=80, W=160] fp32. out: [N, 81, H, W] fp32.
//
// R13 (207us): occ3 persistent + cp.async + batched barriers. Profile: issue 67,
//   L1 60.5, fma 53-of-pipe; ~16% capacity lost to the 640-unit/444-slot tail.
// R14: split-C two-stage. 1280 units = (row, c-half); kernel1 writes raw partial
//   sums to __device__ scratch; kernel2 combines (pA+pB)*scale + leaky, float4.
//   Balanced makespan 2.88 half-units/slot vs 1.44 rows + full-row tail.
//   Shuffle-b and LDS.64 schemes analyzed and rejected: crossbar bytes drop but
//   issue count rises 20-33% and issue is co-binding.

#define MAXD 4
#define DD   9
#define NCH  81
#define C_   256
#define H_   80
#define W_   160
#define N_   8
#define HW_  (H_ * W_)
#define NROWS (N_ * H_)          // 640
#define NUNITS (NROWS * 2)       // 1280: unit = (row, channel-half)
#define CHALF (C_ / 2)           // 128
#define CC   4
#define P_   5
#define F2W  (W_ + 2*MAXD)       // 168
#define NQ4  (F2W / 4)           // 42
#define NTHREADS (DD * 32)       // 288
#define NCHUNK_U (CHALF / CC)    // 32 chunks per unit
#define BATCH 4
#define NBATCH_U (NCHUNK_U / BATCH)  // 8
#define NBLOCKS (148 * 3)        // 444 persistent blocks, 3 CTAs/SM
#define OUTELEMS (N_ * NCH * HW_)    // 8294400

#define S1_FLOATS (2 * BATCH * CC * W_)     // 5120
#define S2_FLOATS (2 * CC * DD * F2W)       // 12096
#define SMEM_BYTES ((S1_FLOATS + S2_FLOATS) * 4)  // 68864 B

__device__ int g_unit_ctr;
__device__ float g_partial[2 * OUTELEMS];   // 66.4MB scratch (c-half partials)

__global__ void reset_ctr_kernel() { g_unit_ctr = 0; }

__device__ __forceinline__ void cp16(float* dst_smem, const float* src_gmem) {
    unsigned d = (unsigned)__cvta_generic_to_shared(dst_smem);
    asm volatile("cp.async.cg.shared.global [%0], [%1], 16;" :: "r"(d), "l"(src_gmem));
}
#define CP_COMMIT() asm volatile("cp.async.commit_group;")
#define CP_WAIT0()  asm volatile("cp.async.wait_group 0;" ::: "memory")

__global__ __launch_bounds__(NTHREADS, 3)
void corr_partial_kernel(const float* __restrict__ f1,
                         const float* __restrict__ f2)
{
    extern __shared__ __align__(16) float smem[];
    float* s1 = smem;               // [2][BATCH][CC][W_]
    float* s2 = smem + S1_FLOATS;   // [2][CC][DD][F2W]
#define S1REF(kb2,s,c,x) s1[((((kb2)*BATCH + (s))*CC + (c))*W_) + (x)]
#define S2REF(b,c,r,j)   s2[(((b)*CC + (c))*DD + (r))*F2W + (j)]
    __shared__ int s_unit;

    const int tid  = threadIdx.x;
    const int dy   = tid >> 5;
    const int lane = tid & 31;
    const int x0   = lane * P_;

    for (;;) {
        if (tid == 0) s_unit = atomicAdd(&g_unit_ctr, 1);
        __syncthreads();
        const int unit = s_unit;     // end-of-unit barrier orders next rewrite
        if (unit >= NUNITS) break;

        const int row   = unit >> 1;
        const int chalf = unit & 1;
        const int n = row / H_;
        const int y = row - n * H_;

        const int img_base = n * C_ * HW_ + chalf * CHALF * HW_;
        const int  gy    = y + dy - MAXD;
        const bool rowok = ((unsigned)gy < (unsigned)H_);
        const float* f1base = f1 + img_base + y * W_;
        const float* f2base = f2 + img_base + gy * W_;

        // pad slots (fixed borders) of this warp's s2 rows, both buffers
        if (rowok) {
            const float4 z4 = make_float4(0.f, 0.f, 0.f, 0.f);
#pragma unroll
            for (int b = 0; b < 2; b++)
#pragma unroll
                for (int c = 0; c < CC; c++) {
                    if (lane == 0) *(float4*)&S2REF(b, c, dy, 0) = z4;
                    if (lane == 1) *(float4*)&S2REF(b, c, dy, 4 * (NQ4 - 1)) = z4;
                }
        }

        float acc[P_][DD];
#pragma unroll
        for (int p = 0; p < P_; p++)
#pragma unroll
            for (int dx = 0; dx < DD; dx++) acc[p][dx] = 0.0f;

        // ---- prologue: stage s1 batch 0 + s2 chunk 0 ----
        for (int q = tid; q < BATCH * CC * (W_ / 4); q += NTHREADS) {
            const int s   = q / (CC * (W_ / 4));
            const int rem = q - s * (CC * (W_ / 4));
            const int c   = rem / (W_ / 4);
            const int j4  = rem - c * (W_ / 4);
            cp16(&S1REF(0, s, c, 4 * j4), f1base + (s * CC + c) * HW_ + 4 * j4);
        }
        if (rowok) {
#pragma unroll
            for (int c = 0; c < CC; c++) {
                const float* rowp = f2base + c * HW_;
                if (lane >= 1) cp16(&S2REF(0, c, dy, 4 * lane),        rowp + 4 * lane - 4);
                if (lane <= 8) cp16(&S2REF(0, c, dy, 4 * (32 + lane)), rowp + 4 * (32 + lane) - 4);
            }
        }
        CP_COMMIT();

#pragma unroll 4
        for (int i = 0; i < NCHUNK_U; i++) {
            const int cur = i & 1;            // compile-time under unroll 4
            CP_WAIT0();
            if ((i & 3) == 0) {
                __syncthreads();               // publish s1 batch i/4
                const int kb = i >> 2;
                if (kb + 1 < NBATCH_U) {       // stage s1 batch kb+1
                    const int cbase = (kb + 1) * BATCH * CC;
                    for (int q = tid; q < BATCH * CC * (W_ / 4); q += NTHREADS) {
                        const int s   = q / (CC * (W_ / 4));
                        const int rem = q - s * (CC * (W_ / 4));
                        const int c   = rem / (W_ / 4);
                        const int j4  = rem - c * (W_ / 4);
                        cp16(&S1REF((kb + 1) & 1, s, c, 4 * j4),
                             f1base + (cbase + s * CC + c) * HW_ + 4 * j4);
                    }
                }
            } else {
                __syncwarp();                  // s2 warp-private publish
            }

            if (i + 1 < NCHUNK_U && rowok) {   // stage s2 chunk i+1
                const int nb = cur ^ 1;
                const int c0 = (i + 1) * CC;
#pragma unroll
                for (int c = 0; c < CC; c++) {
                    const float* rowp = f2base + (c0 + c) * HW_;
                    if (lane >= 1) cp16(&S2REF(nb, c, dy, 4 * lane),        rowp + 4 * lane - 4);
                    if (lane <= 8) cp16(&S2REF(nb, c, dy, 4 * (32 + lane)), rowp + 4 * (32 + lane) - 4);
                }
            }
            CP_COMMIT();

            // compute chunk i (skipped for OOB rows: acc stays 0)
            if (rowok) {
                const int kb2 = (i >> 2) & 1;
                const int slt = i & 3;
#pragma unroll
                for (int cc = 0; cc < CC; cc++) {
                    const float* s1row = &S1REF(kb2, slt, cc, x0);
                    const float* s2row = &S2REF(cur, cc, dy, x0);
                    float a[P_];
#pragma unroll
                    for (int p = 0; p < P_; p++) a[p] = s1row[p];
#pragma unroll
                    for (int k = 0; k < P_ + DD - 1; k++) {
                        const float bk = s2row[k];
                        const int plo = (k - (DD - 1)) > 0 ? (k - (DD - 1)) : 0;
                        const int phi = k < (P_ - 1) ? k : (P_ - 1);
#pragma unroll
                        for (int p = plo; p <= phi; p++)
                            acc[p][k - p] = fmaf(a[p], bk, acc[p][k - p]);
                    }
                }
            }
        }

        // epilogue: raw partial sums to scratch (scale+leaky applied in combine)
        float* pbase = g_partial + chalf * OUTELEMS + n * NCH * HW_ + y * W_;
#pragma unroll
        for (int dx = 0; dx < DD; dx++) {
            const int ch = dy * DD + dx;
            float* prow = pbase + ch * HW_;
#pragma unroll
            for (int p = 0; p < P_; p++)
                prow[x0 + p] = acc[p][dx];
        }

        __syncthreads();   // all reads done before smem rebind / s_unit rewrite
    }
}

// kernel2: out = leaky((pA + pB) / C), vectorized float4
__global__ __launch_bounds__(256)
void combine_kernel(float* __restrict__ out)
{
    const int i = blockIdx.x * 256 + threadIdx.x;   // 0 .. OUTELEMS/4-1
    const float4 a = ((const float4*)g_partial)[i];
    const float4 b = ((const float4*)(g_partial + OUTELEMS))[i];
    const float scale = 1.0f / (float)C_;
    float4 v;
    float t;
    t = (a.x + b.x) * scale; v.x = (t > 0.0f) ? t : 0.1f * t;
    t = (a.y + b.y) * scale; v.y = (t > 0.0f) ? t : 0.1f * t;
    t = (a.z + b.z) * scale; v.z = (t > 0.0f) ? t : 0.1f * t;
    t = (a.w + b.w) * scale; v.w = (t > 0.0f) ? t : 0.1f * t;
    ((float4*)out)[i] = v;
}

extern "C" void kernel_launch(void* const* d_in, const int* in_sizes, int n_in,
                              void* d_out, int out_size)
{
    const float* feat1 = (const float*)d_in[0];
    const float* feat2 = (const float*)d_in[1];
    float* out = (float*)d_out;
    cudaFuncSetAttribute(corr_partial_kernel,
                         cudaFuncAttributeMaxDynamicSharedMemorySize, SMEM_BYTES);
    reset_ctr_kernel<<<1, 1>>>();
    corr_partial_kernel<<<NBLOCKS, NTHREADS, SMEM_BYTES>>>(feat1, feat2);
    combine_kernel<<<(OUTELEMS / 4) / 256, 256>>>(out);
}